// round 10
// baseline (speedup 1.0000x reference)
#include <cuda_runtime.h>
#include <cuda_bf16.h>
#include <cstdint>
#include <cstddef>

#define NROWS   8192
#define DMODEL  768
#define DDICT   24576
#define TOPK    32
#define NCAND   48
#define CAP     1024
#define TIE_EPS 1.0e-6

// GEMM tiling (mma.sync): CTA 128x256, 512 threads, warp tile 64x32, BK=32
#define GBM 128
#define GBN 256
#define GBK 32
#define NIT (DMODEL / GBK)          // 24
#define LDS 80                      // smem row pitch: 32 bf16 (64B) + 16B pad
#define A_STAGE (GBM * LDS)         // 10240 B
#define B_STAGE (GBN * LDS)         // 20480 B
#define STAGE_BYTES (A_STAGE + B_STAGE)   // 30720 B
#define NSTAGE 3
#define SMEM_TOTAL_G (NSTAGE * STAGE_BYTES)   // 92160 B

// ---------------- scratch (static device arrays; no cudaMalloc) ----------------
__device__ __align__(16) __nv_bfloat16  g_xb[(size_t)NROWS * DMODEL];
__device__ __align__(16) __nv_bfloat16  g_wb[(size_t)DDICT * DMODEL];
__device__ float    g_WdecT[(size_t)DDICT * DMODEL];
__device__ float    g_vals[NROWS * TOPK];
__device__ int      g_idx [NROWS * TOPK];
__device__ int      g_cand[NROWS * NCAND];
__device__ uint32_t g_cbuf[(size_t)NROWS * CAP];
__device__ int      g_ccnt[NROWS];
__device__ uint16_t g_tkey[NROWS];

// ---------------- order-preserving bf16 key ----------------
__device__ __forceinline__ uint16_t key1(float v)
{
    uint16_t r = __bfloat16_as_ushort(__float2bfloat16_rn(v));
    uint16_t mask = (r & 0x8000u) ? 0xFFFFu : 0x8000u;
    return (uint16_t)(r ^ mask);
}

// ---------------- per-row threshold + counter reset ----------------
__global__ __launch_bounds__(256) void row_thresh_kernel(
    const float* __restrict__ x, uint16_t* __restrict__ tkey, int* __restrict__ ccnt)
{
    const int row  = blockIdx.x * 8 + (threadIdx.x >> 5);
    const int lane = threadIdx.x & 31;
    const float* xr = x + (size_t)row * DMODEL;
    float s = 0.f;
#pragma unroll
    for (int d = lane; d < DMODEL; d += 32) { float v = xr[d]; s = fmaf(v, v, s); }
#pragma unroll
    for (int off = 16; off > 0; off >>= 1)
        s += __shfl_down_sync(0xFFFFFFFFu, s, off);
    if (lane == 0) {
        float sigma = sqrtf(s * (1.0f / DMODEL));
        float t = 2.55f * sigma - 0.06f;
        tkey[row] = key1(t);
        ccnt[row] = 0;
    }
}

// ---------------- fp32 -> bf16 conversion ----------------
__global__ __launch_bounds__(256) void convert_bf16_kernel(
    const float* __restrict__ src, __nv_bfloat16* __restrict__ dst, int n4)
{
    int i = blockIdx.x * 256 + threadIdx.x;
    if (i < n4) {
        float4 v = reinterpret_cast<const float4*>(src)[i];
        uint32_t p0, p1;
        asm("cvt.rn.bf16x2.f32 %0, %1, %2;" : "=r"(p0) : "f"(v.y), "f"(v.x));
        asm("cvt.rn.bf16x2.f32 %0, %1, %2;" : "=r"(p1) : "f"(v.w), "f"(v.z));
        reinterpret_cast<uint2*>(dst)[i] = make_uint2(p0, p1);
    }
}

// ---------------- W_dec transpose ----------------
__global__ __launch_bounds__(256) void transpose_wdec_kernel(
    const float* __restrict__ Wdec, float* __restrict__ WdecT)
{
    __shared__ float tile[32][33];
    int x = blockIdx.x * 32 + threadIdx.x;
    int y = blockIdx.y * 32 + threadIdx.y;
#pragma unroll
    for (int j = 0; j < 32; j += 8)
        tile[threadIdx.y + j][threadIdx.x] = Wdec[(size_t)(y + j) * DDICT + x];
    __syncthreads();
    int xo = blockIdx.y * 32 + threadIdx.x;
    int yo = blockIdx.x * 32 + threadIdx.y;
#pragma unroll
    for (int j = 0; j < 32; j += 8)
        WdecT[(size_t)(yo + j) * DMODEL + xo] = tile[threadIdx.x][threadIdx.y + j];
}

// ---------------- mma.sync helpers (proven round-5 mapping) ----------------
__device__ __forceinline__ void ldsm_x4(uint32_t& r0, uint32_t& r1, uint32_t& r2,
                                        uint32_t& r3, uint32_t a)
{
    asm volatile("ldmatrix.sync.aligned.m8n8.x4.shared.b16 {%0,%1,%2,%3}, [%4];"
                 : "=r"(r0), "=r"(r1), "=r"(r2), "=r"(r3) : "r"(a));
}

__device__ __forceinline__ void mma_16816(float* c, uint32_t a0, uint32_t a1,
                                          uint32_t a2, uint32_t a3,
                                          uint32_t b0, uint32_t b1)
{
    asm volatile("mma.sync.aligned.m16n8k16.row.col.f32.bf16.bf16.f32 "
                 "{%0,%1,%2,%3}, {%4,%5,%6,%7}, {%8,%9}, {%0,%1,%2,%3};"
                 : "+f"(c[0]), "+f"(c[1]), "+f"(c[2]), "+f"(c[3])
                 : "r"(a0), "r"(a1), "r"(a2), "r"(a3), "r"(b0), "r"(b1));
}

__device__ __forceinline__ void push_cand(int row, int col, float v, uint16_t tk,
                                          int* ccnt, uint32_t* cbuf)
{
    uint16_t k = key1(v);
    if (k > tk) {
        int pos = atomicAdd(&ccnt[row], 1);
        if (pos < CAP)
            cbuf[(size_t)row * CAP + pos] = ((uint32_t)k << 15) | (uint32_t)col;
    }
}

#define CPA16(dst, src) asm volatile( \
    "cp.async.cg.shared.global [%0], [%1], 16;" :: "r"(dst), "l"(src))

// ---------------- bf16 candidate GEMM: 128x256 CTA, 512 thr, 3-stage ----------
__global__ __launch_bounds__(512, 1) void gemm_bf16_kernel(
    const __nv_bfloat16* __restrict__ A,   // xb  [NROWS, DMODEL]
    const __nv_bfloat16* __restrict__ B,   // wb  [DDICT, DMODEL]
    const float* __restrict__ bias,
    const uint16_t* __restrict__ tkey,
    int* __restrict__ ccnt,
    uint32_t* __restrict__ cbuf)
{
    extern __shared__ __align__(16) unsigned char smem[];
    const uint32_t sbase = (uint32_t)__cvta_generic_to_shared(smem);

    const int tid  = threadIdx.x;
    const int lane = tid & 31;
    const int wid  = tid >> 5;             // 0..15
    const int bm   = blockIdx.y * GBM;
    const int bn   = blockIdx.x * GBN;
    const int wm   = (wid & 1) * 64;       // 2 warps in M
    const int wn   = (wid >> 1) * 32;      // 8 warps in N -> 256

    // cp.async assignment: 512 threads, each 1 A seg + 2 B segs of 16B per chunk
    const int r0 = tid >> 2;               // 0..127
    const int c8 = (tid & 3) * 8;          // bf16 col offset 0,8,16,24
    const __nv_bfloat16* gA  = A + (size_t)(bm + r0)       * DMODEL + c8;
    const __nv_bfloat16* gB0 = B + (size_t)(bn + r0)       * DMODEL + c8;
    const __nv_bfloat16* gB1 = B + (size_t)(bn + r0 + 128) * DMODEL + c8;
    const uint32_t dA  = r0 * LDS + c8 * 2;
    const uint32_t dB0 = A_STAGE + r0 * LDS + c8 * 2;
    const uint32_t dB1 = A_STAGE + (r0 + 128) * LDS + c8 * 2;

    // ldmatrix per-thread address components (round-5 proven)
    const int rowin = (lane & 7) + ((lane >> 3) & 1) * 8;   // A row within 16
    const int kxa   = (lane >> 4) * 16;                     // A k-byte half
    const int rowb  = wn + (lane >> 4) * 8 + (lane & 7);    // B row (tile pair)
    const int kxb   = ((lane >> 3) & 1) * 16;               // B k-byte half

    float acc[4][4][4];
#pragma unroll
    for (int i = 0; i < 4; i++)
#pragma unroll
        for (int j = 0; j < 4; j++)
#pragma unroll
            for (int q = 0; q < 4; q++) acc[i][j][q] = 0.f;

    auto load_chunk = [&](int c, int s) {
        const uint32_t st = sbase + s * STAGE_BYTES;
        const int ke = c * GBK;
        CPA16(st + dA,  gA  + ke);
        CPA16(st + dB0, gB0 + ke);
        CPA16(st + dB1, gB1 + ke);
        asm volatile("cp.async.commit_group;");
    };

    // prologue: chunks 0,1 -> stages 0,1
    load_chunk(0, 0);
    load_chunk(1, 1);

    for (int c = 0; c < NIT; c++) {
        if (c == NIT - 1) asm volatile("cp.async.wait_group 0;");
        else              asm volatile("cp.async.wait_group 1;");
        __syncthreads();   // chunk c resident; all warps done with stage (c+2)%3

        if (c + 2 < NIT) load_chunk(c + 2, (c + 2) % 3);

        const uint32_t st = sbase + (c % 3) * STAGE_BYTES;
        const uint32_t aB = st;
        const uint32_t bB = st + A_STAGE;
#pragma unroll
        for (int ks = 0; ks < 2; ks++) {
            uint32_t af[4][4];
#pragma unroll
            for (int mt = 0; mt < 4; mt++)
                ldsm_x4(af[mt][0], af[mt][1], af[mt][2], af[mt][3],
                        aB + (uint32_t)((wm + mt * 16 + rowin) * LDS + ks * 32 + kxa));
            uint32_t bf[4][2];
#pragma unroll
            for (int p = 0; p < 2; p++) {
                uint32_t t0, t1, t2, t3;
                ldsm_x4(t0, t1, t2, t3,
                        bB + (uint32_t)((rowb + p * 16) * LDS + ks * 32 + kxb));
                bf[2 * p][0] = t0; bf[2 * p][1] = t1;
                bf[2 * p + 1][0] = t2; bf[2 * p + 1][1] = t3;
            }
#pragma unroll
            for (int mt = 0; mt < 4; mt++)
#pragma unroll
                for (int nt = 0; nt < 4; nt++)
                    mma_16816(acc[mt][nt], af[mt][0], af[mt][1], af[mt][2],
                              af[mt][3], bf[nt][0], bf[nt][1]);
        }
        __syncthreads();
    }

    // epilogue: +bias, threshold-compare, push candidates (round-7 proven)
    float bb0[4], bb1[4];
    int   ncol[4];
#pragma unroll
    for (int nt = 0; nt < 4; nt++) {
        ncol[nt] = bn + wn + nt * 8 + (lane & 3) * 2;
        bb0[nt] = bias[ncol[nt]];
        bb1[nt] = bias[ncol[nt] + 1];
    }
#pragma unroll
    for (int mt = 0; mt < 4; mt++) {
        const int mlo = bm + wm + mt * 16 + (lane >> 2);
        const int mhi = mlo + 8;
        const uint16_t tlo = tkey[mlo];
        const uint16_t thi = tkey[mhi];
#pragma unroll
        for (int nt = 0; nt < 4; nt++) {
            push_cand(mlo, ncol[nt],     acc[mt][nt][0] + bb0[nt], tlo, ccnt, cbuf);
            push_cand(mlo, ncol[nt] + 1, acc[mt][nt][1] + bb1[nt], tlo, ccnt, cbuf);
            push_cand(mhi, ncol[nt],     acc[mt][nt][2] + bb0[nt], thi, ccnt, cbuf);
            push_cand(mhi, ncol[nt] + 1, acc[mt][nt][3] + bb1[nt], thi, ccnt, cbuf);
        }
    }
}

// ---------------- top-48 of candidate pool ----------------
__global__ __launch_bounds__(256) void top48_kernel(
    const int* __restrict__ ccnt, const uint32_t* __restrict__ cbuf,
    int* __restrict__ cand)
{
    __shared__ uint32_t sp[CAP];
    const int n = blockIdx.x, tid = threadIdx.x;
    const int cnt = min(ccnt[n], CAP);
    for (int i = tid; i < cnt; i += 256) sp[i] = cbuf[(size_t)n * CAP + i];
    __syncthreads();
    for (int t = tid; t < cnt; t += 256) {
        const uint32_t p = sp[t];
        int rank = 0;
        for (int u = 0; u < cnt; u++) rank += (sp[u] > p);
        if (rank < NCAND) cand[n * NCAND + rank] = (int)(p & 0x7FFFu);
    }
    for (int t = tid; t < NCAND; t += 256)
        if (t >= cnt) cand[n * NCAND + t] = t;
}

// ---------------- exact rescore (fp64) + top-32 w/ boundary rule ----------------
__global__ __launch_bounds__(256) void rescore_kernel(
    const float* __restrict__ X, const float* __restrict__ W,
    const float* __restrict__ bias, const int* __restrict__ cand,
    float* __restrict__ vals, int* __restrict__ idxs)
{
    __shared__ float  sx[DMODEL];
    __shared__ double sv[NCAND];
    __shared__ int    si[NCAND];
    __shared__ int    s_rank[NCAND];
    __shared__ int    s_c31, s_c32;

    const int n    = blockIdx.x;
    const int tid  = threadIdx.x;
    const int wid  = tid >> 5;
    const int lane = tid & 31;

    for (int i = tid; i < DMODEL; i += 256) sx[i] = X[(size_t)n * DMODEL + i];
    if (tid < NCAND) si[tid] = cand[n * NCAND + tid];
    __syncthreads();

    for (int c = wid * 6; c < wid * 6 + 6; c++) {
        const int f = si[c];
        const float* w = W + (size_t)f * DMODEL;
        double acc = 0.0;
#pragma unroll
        for (int d = lane; d < DMODEL; d += 32)
            acc += (double)sx[d] * (double)__ldg(&w[d]);
#pragma unroll
        for (int off = 16; off > 0; off >>= 1)
            acc += __shfl_down_sync(0xFFFFFFFFu, acc, off);
        if (lane == 0) sv[c] = acc + (double)bias[f];
    }
    __syncthreads();

    if (tid < NCAND) {
        const double v  = sv[tid];
        const int    mi = si[tid];
        int rank = 0;
#pragma unroll
        for (int u = 0; u < NCAND; u++) {
            double vu = sv[u];
            rank += (vu > v) || (vu == v && si[u] < mi);
        }
        s_rank[tid] = rank;
        if (rank == TOPK - 1) s_c31 = tid;
        if (rank == TOPK)     s_c32 = tid;
    }
    __syncthreads();

    if (tid == 0) {
        int c31 = s_c31, c32 = s_c32;
        if (fabs(sv[c31] - sv[c32]) <= TIE_EPS && si[c32] < si[c31]) {
            s_rank[c31] = TOPK;
            s_rank[c32] = TOPK - 1;
        }
    }
    __syncthreads();

    if (tid < NCAND) {
        int rank = s_rank[tid];
        if (rank < TOPK) {
            vals[n * TOPK + rank] = fmaxf((float)sv[tid], 0.f);
            idxs[n * TOPK + rank] = si[tid];
        }
    }
}

// ---------------- fused output: zero+scatter sparse, decode ----------------
__global__ __launch_bounds__(256) void output_kernel(
    const float* __restrict__ vals, const int* __restrict__ idxs,
    const float* __restrict__ WdecT, const float* __restrict__ b_dec,
    float* __restrict__ xhat, float* __restrict__ sparse)
{
    const int n   = blockIdx.x;
    const int tid = threadIdx.x;
    __shared__ float sv[TOPK];
    __shared__ int   si[TOPK];
    if (tid < TOPK) { sv[tid] = vals[n * TOPK + tid]; si[tid] = idxs[n * TOPK + tid]; }
    __syncthreads();

    float4* row4 = reinterpret_cast<float4*>(sparse + (size_t)n * DDICT);
    const float4 z4 = make_float4(0.f, 0.f, 0.f, 0.f);
    for (int i = tid; i < DDICT / 4; i += 256) row4[i] = z4;

    float a0 = b_dec[tid], a1 = b_dec[tid + 256], a2 = b_dec[tid + 512];
#pragma unroll
    for (int k = 0; k < TOPK; k++) {
        const float* w = WdecT + (size_t)si[k] * DMODEL;
        const float v = sv[k];
        a0 = fmaf(v, w[tid],       a0);
        a1 = fmaf(v, w[tid + 256], a1);
        a2 = fmaf(v, w[tid + 512], a2);
    }
    float* o = xhat + (size_t)n * DMODEL;
    o[tid] = a0; o[tid + 256] = a1; o[tid + 512] = a2;

    __syncthreads();
    if (tid < TOPK)
        sparse[(size_t)n * DDICT + si[tid]] = sv[tid];
}

// ---------------- launch ----------------
extern "C" void kernel_launch(void* const* d_in, const int* in_sizes, int n_in,
                              void* d_out, int out_size)
{
    const float* x     = (const float*)d_in[0];
    const float* W_enc = (const float*)d_in[1];
    const float* b_enc = (const float*)d_in[2];
    const float* W_dec = (const float*)d_in[3];
    const float* b_dec = (const float*)d_in[4];

    float* xhat   = (float*)d_out;
    float* sparse = (float*)d_out + (size_t)NROWS * DMODEL;

    __nv_bfloat16* xb; cudaGetSymbolAddress((void**)&xb, g_xb);
    __nv_bfloat16* wb; cudaGetSymbolAddress((void**)&wb, g_wb);
    float*    WdecT; cudaGetSymbolAddress((void**)&WdecT, g_WdecT);
    float*    vals;  cudaGetSymbolAddress((void**)&vals,  g_vals);
    int*      idx;   cudaGetSymbolAddress((void**)&idx,   g_idx);
    int*      cand;  cudaGetSymbolAddress((void**)&cand,  g_cand);
    uint32_t* cbuf;  cudaGetSymbolAddress((void**)&cbuf,  g_cbuf);
    int*      ccnt;  cudaGetSymbolAddress((void**)&ccnt,  g_ccnt);
    uint16_t* tkey;  cudaGetSymbolAddress((void**)&tkey,  g_tkey);

    row_thresh_kernel<<<NROWS / 8, 256>>>(x, tkey, ccnt);

    {
        int n4 = NROWS * DMODEL / 4;
        convert_bf16_kernel<<<(n4 + 255) / 256, 256>>>(x, xb, n4);
        n4 = DDICT * DMODEL / 4;
        convert_bf16_kernel<<<(n4 + 255) / 256, 256>>>(W_enc, wb, n4);
    }

    transpose_wdec_kernel<<<dim3(DDICT / 32, DMODEL / 32), dim3(32, 8)>>>(W_dec, WdecT);

    // bf16 tensor-core candidate GEMM (128x256 tile, 3-stage)
    cudaFuncSetAttribute(gemm_bf16_kernel, cudaFuncAttributeMaxDynamicSharedMemorySize,
                         SMEM_TOTAL_G);
    gemm_bf16_kernel<<<dim3(DDICT / GBN, NROWS / GBM), 512, SMEM_TOTAL_G>>>(
        xb, wb, b_enc, tkey, ccnt, cbuf);

    top48_kernel<<<NROWS, 256>>>(ccnt, cbuf, cand);

    rescore_kernel<<<NROWS, 256>>>(x, W_enc, b_enc, cand, vals, idx);

    output_kernel<<<NROWS, 256>>>(vals, idx, WdecT, b_dec, xhat, sparse);
}

// round 11
// speedup vs baseline: 1.0828x; 1.0828x over previous
#include <cuda_runtime.h>
#include <cuda_bf16.h>
#include <cstdint>
#include <cstddef>

#define NROWS   8192
#define DMODEL  768
#define DDICT   24576
#define TOPK    32
#define NCAND   48
#define CAP     1024
#define TIE_EPS 1.0e-6

// GEMM tiling (mma.sync): CTA 128x128, 256 threads, warp tile 64x32, BK=32
#define GBK 32
#define NIT (DMODEL / GBK)            // 24
#define LDS 80                        // smem row pitch: 32 bf16 (64B) + 16B pad
#define A_ST (128 * LDS)              // 10240 B
#define STAGE_BYTES (2 * A_ST)        // A + B = 20480 B
#define NSTAGE 3
#define SMEM_TOTAL_G (NSTAGE * STAGE_BYTES)   // 61440 B

// ---------------- scratch (static device arrays; no cudaMalloc) ----------------
__device__ __align__(16) __nv_bfloat16  g_xb[(size_t)NROWS * DMODEL];
__device__ __align__(16) __nv_bfloat16  g_wb[(size_t)DDICT * DMODEL];
__device__ float    g_WdecT[(size_t)DDICT * DMODEL];
__device__ float    g_vals[NROWS * TOPK];
__device__ int      g_idx [NROWS * TOPK];
__device__ int      g_cand[NROWS * NCAND];
__device__ uint32_t g_cbuf[(size_t)NROWS * CAP];
__device__ int      g_ccnt[NROWS];
__device__ uint16_t g_tkey[NROWS];

// ---------------- order-preserving bf16 key ----------------
__device__ __forceinline__ uint16_t key1(float v)
{
    uint16_t r = __bfloat16_as_ushort(__float2bfloat16_rn(v));
    uint16_t mask = (r & 0x8000u) ? 0xFFFFu : 0x8000u;
    return (uint16_t)(r ^ mask);
}

// ---------------- per-row threshold + counter reset ----------------
__global__ __launch_bounds__(256) void row_thresh_kernel(
    const float* __restrict__ x, uint16_t* __restrict__ tkey, int* __restrict__ ccnt)
{
    const int row  = blockIdx.x * 8 + (threadIdx.x >> 5);
    const int lane = threadIdx.x & 31;
    const float* xr = x + (size_t)row * DMODEL;
    float s = 0.f;
#pragma unroll
    for (int d = lane; d < DMODEL; d += 32) { float v = xr[d]; s = fmaf(v, v, s); }
#pragma unroll
    for (int off = 16; off > 0; off >>= 1)
        s += __shfl_down_sync(0xFFFFFFFFu, s, off);
    if (lane == 0) {
        float sigma = sqrtf(s * (1.0f / DMODEL));
        float t = 2.55f * sigma - 0.06f;
        tkey[row] = key1(t);
        ccnt[row] = 0;
    }
}

// ---------------- fp32 -> bf16 conversion ----------------
__global__ __launch_bounds__(256) void convert_bf16_kernel(
    const float* __restrict__ src, __nv_bfloat16* __restrict__ dst, int n4)
{
    int i = blockIdx.x * 256 + threadIdx.x;
    if (i < n4) {
        float4 v = reinterpret_cast<const float4*>(src)[i];
        uint32_t p0, p1;
        asm("cvt.rn.bf16x2.f32 %0, %1, %2;" : "=r"(p0) : "f"(v.y), "f"(v.x));
        asm("cvt.rn.bf16x2.f32 %0, %1, %2;" : "=r"(p1) : "f"(v.w), "f"(v.z));
        reinterpret_cast<uint2*>(dst)[i] = make_uint2(p0, p1);
    }
}

// ---------------- W_dec transpose ----------------
__global__ __launch_bounds__(256) void transpose_wdec_kernel(
    const float* __restrict__ Wdec, float* __restrict__ WdecT)
{
    __shared__ float tile[32][33];
    int x = blockIdx.x * 32 + threadIdx.x;
    int y = blockIdx.y * 32 + threadIdx.y;
#pragma unroll
    for (int j = 0; j < 32; j += 8)
        tile[threadIdx.y + j][threadIdx.x] = Wdec[(size_t)(y + j) * DDICT + x];
    __syncthreads();
    int xo = blockIdx.y * 32 + threadIdx.x;
    int yo = blockIdx.x * 32 + threadIdx.y;
#pragma unroll
    for (int j = 0; j < 32; j += 8)
        WdecT[(size_t)(yo + j) * DMODEL + xo] = tile[threadIdx.x][threadIdx.y + j];
}

// ---------------- mma.sync helpers (proven round-5 mapping) ----------------
__device__ __forceinline__ void ldsm_x4(uint32_t& r0, uint32_t& r1, uint32_t& r2,
                                        uint32_t& r3, uint32_t a)
{
    asm volatile("ldmatrix.sync.aligned.m8n8.x4.shared.b16 {%0,%1,%2,%3}, [%4];"
                 : "=r"(r0), "=r"(r1), "=r"(r2), "=r"(r3) : "r"(a));
}

__device__ __forceinline__ void mma_16816(float* c, uint32_t a0, uint32_t a1,
                                          uint32_t a2, uint32_t a3,
                                          uint32_t b0, uint32_t b1)
{
    asm volatile("mma.sync.aligned.m16n8k16.row.col.f32.bf16.bf16.f32 "
                 "{%0,%1,%2,%3}, {%4,%5,%6,%7}, {%8,%9}, {%0,%1,%2,%3};"
                 : "+f"(c[0]), "+f"(c[1]), "+f"(c[2]), "+f"(c[3])
                 : "r"(a0), "r"(a1), "r"(a2), "r"(a3), "r"(b0), "r"(b1));
}

__device__ __forceinline__ void push_cand(int row, int col, float v, uint16_t tk,
                                          int* ccnt, uint32_t* cbuf)
{
    uint16_t k = key1(v);
    if (k > tk) {
        int pos = atomicAdd(&ccnt[row], 1);
        if (pos < CAP)
            cbuf[(size_t)row * CAP + pos] = ((uint32_t)k << 15) | (uint32_t)col;
    }
}

#define CPA16(dst, src) asm volatile( \
    "cp.async.cg.shared.global [%0], [%1], 16;" :: "r"(dst), "l"(src))

// ---------------- bf16 candidate GEMM: 128x128 CTA, 256 thr, 3-stage ----------
__global__ __launch_bounds__(256) void gemm_bf16_kernel(
    const __nv_bfloat16* __restrict__ A,   // xb  [NROWS, DMODEL]
    const __nv_bfloat16* __restrict__ B,   // wb  [DDICT, DMODEL]
    const float* __restrict__ bias,
    const uint16_t* __restrict__ tkey,
    int* __restrict__ ccnt,
    uint32_t* __restrict__ cbuf)
{
    extern __shared__ __align__(16) unsigned char smem[];
    const uint32_t sbase = (uint32_t)__cvta_generic_to_shared(smem);

    const int tid  = threadIdx.x;
    const int lane = tid & 31;
    const int wid  = tid >> 5;
    const int bm   = blockIdx.y * 128;
    const int bn   = blockIdx.x * 128;
    const int wm   = (wid & 1) * 64;        // 2 warps in M
    const int wn   = (wid >> 1) * 32;       // 4 warps in N

    // cp.async: each thread copies 2x16B of A and 2x16B of B per K-chunk
    const int r0 = tid >> 2, c8 = (tid & 3) * 8;
    const __nv_bfloat16* gA0 = A + (size_t)(bm + r0)      * DMODEL + c8;
    const __nv_bfloat16* gA1 = A + (size_t)(bm + r0 + 64) * DMODEL + c8;
    const __nv_bfloat16* gB0 = B + (size_t)(bn + r0)      * DMODEL + c8;
    const __nv_bfloat16* gB1 = B + (size_t)(bn + r0 + 64) * DMODEL + c8;
    const uint32_t dA0 = r0 * LDS + c8 * 2;
    const uint32_t dA1 = (r0 + 64) * LDS + c8 * 2;

    // ldmatrix per-thread address components (round-5 proven)
    const int rowin = (lane & 7) + ((lane >> 3) & 1) * 8;   // A row within 16
    const int kxa   = (lane >> 4) * 16;                     // A k-byte half
    const int rowb  = wn + (lane >> 4) * 8 + (lane & 7);    // B row (tile pair)
    const int kxb   = ((lane >> 3) & 1) * 16;               // B k-byte half

    float acc[4][4][4];
#pragma unroll
    for (int i = 0; i < 4; i++)
#pragma unroll
        for (int j = 0; j < 4; j++)
#pragma unroll
            for (int q = 0; q < 4; q++) acc[i][j][q] = 0.f;

    auto load_chunk = [&](int c, int s) {
        const uint32_t st = sbase + s * STAGE_BYTES;
        const int ke = c * GBK;
        CPA16(st + dA0, gA0 + ke); CPA16(st + dA1, gA1 + ke);
        CPA16(st + A_ST + dA0, gB0 + ke); CPA16(st + A_ST + dA1, gB1 + ke);
        asm volatile("cp.async.commit_group;");
    };

    // prologue: chunks 0,1 -> stages 0,1
    load_chunk(0, 0);
    load_chunk(1, 1);

    for (int c = 0; c < NIT; c++) {
        if (c + 2 < NIT) {
            // stage (c+2)%3 == stage (c-1)%3: freed by end-of-iter-(c-1) sync
            load_chunk(c + 2, (c + 2) % 3);
            asm volatile("cp.async.wait_group 2;");   // chunk c resident
        } else {
            asm volatile("cp.async.wait_group 0;");
        }
        __syncthreads();

        const uint32_t st = sbase + (c % 3) * STAGE_BYTES;
        const uint32_t aB = st;
        const uint32_t bB = st + A_ST;
#pragma unroll
        for (int ks = 0; ks < 2; ks++) {
            uint32_t af[4][4];
#pragma unroll
            for (int mt = 0; mt < 4; mt++)
                ldsm_x4(af[mt][0], af[mt][1], af[mt][2], af[mt][3],
                        aB + (uint32_t)((wm + mt * 16 + rowin) * LDS + ks * 32 + kxa));
            uint32_t bf[4][2];
#pragma unroll
            for (int p = 0; p < 2; p++) {
                uint32_t t0, t1, t2, t3;
                ldsm_x4(t0, t1, t2, t3,
                        bB + (uint32_t)((rowb + p * 16) * LDS + ks * 32 + kxb));
                bf[2 * p][0] = t0; bf[2 * p][1] = t1;
                bf[2 * p + 1][0] = t2; bf[2 * p + 1][1] = t3;
            }
#pragma unroll
            for (int mt = 0; mt < 4; mt++)
#pragma unroll
                for (int nt = 0; nt < 4; nt++)
                    mma_16816(acc[mt][nt], af[mt][0], af[mt][1], af[mt][2],
                              af[mt][3], bf[nt][0], bf[nt][1]);
        }
        __syncthreads();
    }

    // epilogue: +bias, threshold-compare, push candidates (round-7 proven)
    float bb0[4], bb1[4];
    int   ncol[4];
#pragma unroll
    for (int nt = 0; nt < 4; nt++) {
        ncol[nt] = bn + wn + nt * 8 + (lane & 3) * 2;
        bb0[nt] = bias[ncol[nt]];
        bb1[nt] = bias[ncol[nt] + 1];
    }
#pragma unroll
    for (int mt = 0; mt < 4; mt++) {
        const int mlo = bm + wm + mt * 16 + (lane >> 2);
        const int mhi = mlo + 8;
        const uint16_t tlo = tkey[mlo];
        const uint16_t thi = tkey[mhi];
#pragma unroll
        for (int nt = 0; nt < 4; nt++) {
            push_cand(mlo, ncol[nt],     acc[mt][nt][0] + bb0[nt], tlo, ccnt, cbuf);
            push_cand(mlo, ncol[nt] + 1, acc[mt][nt][1] + bb1[nt], tlo, ccnt, cbuf);
            push_cand(mhi, ncol[nt],     acc[mt][nt][2] + bb0[nt], thi, ccnt, cbuf);
            push_cand(mhi, ncol[nt] + 1, acc[mt][nt][3] + bb1[nt], thi, ccnt, cbuf);
        }
    }
}

// ---------------- top-48 of candidate pool ----------------
__global__ __launch_bounds__(256) void top48_kernel(
    const int* __restrict__ ccnt, const uint32_t* __restrict__ cbuf,
    int* __restrict__ cand)
{
    __shared__ uint32_t sp[CAP];
    const int n = blockIdx.x, tid = threadIdx.x;
    const int cnt = min(ccnt[n], CAP);
    for (int i = tid; i < cnt; i += 256) sp[i] = cbuf[(size_t)n * CAP + i];
    __syncthreads();
    for (int t = tid; t < cnt; t += 256) {
        const uint32_t p = sp[t];
        int rank = 0;
        for (int u = 0; u < cnt; u++) rank += (sp[u] > p);
        if (rank < NCAND) cand[n * NCAND + rank] = (int)(p & 0x7FFFu);
    }
    for (int t = tid; t < NCAND; t += 256)
        if (t >= cnt) cand[n * NCAND + t] = t;
}

// ---------------- exact rescore (fp64) + top-32 w/ boundary rule ----------------
__global__ __launch_bounds__(256) void rescore_kernel(
    const float* __restrict__ X, const float* __restrict__ W,
    const float* __restrict__ bias, const int* __restrict__ cand,
    float* __restrict__ vals, int* __restrict__ idxs)
{
    __shared__ float  sx[DMODEL];
    __shared__ double sv[NCAND];
    __shared__ int    si[NCAND];
    __shared__ int    s_rank[NCAND];
    __shared__ int    s_c31, s_c32;

    const int n    = blockIdx.x;
    const int tid  = threadIdx.x;
    const int wid  = tid >> 5;
    const int lane = tid & 31;

    for (int i = tid; i < DMODEL; i += 256) sx[i] = X[(size_t)n * DMODEL + i];
    if (tid < NCAND) si[tid] = cand[n * NCAND + tid];
    __syncthreads();

    for (int c = wid * 6; c < wid * 6 + 6; c++) {
        const int f = si[c];
        const float* w = W + (size_t)f * DMODEL;
        double acc = 0.0;
#pragma unroll
        for (int d = lane; d < DMODEL; d += 32)
            acc += (double)sx[d] * (double)__ldg(&w[d]);
#pragma unroll
        for (int off = 16; off > 0; off >>= 1)
            acc += __shfl_down_sync(0xFFFFFFFFu, acc, off);
        if (lane == 0) sv[c] = acc + (double)bias[f];
    }
    __syncthreads();

    if (tid < NCAND) {
        const double v  = sv[tid];
        const int    mi = si[tid];
        int rank = 0;
#pragma unroll
        for (int u = 0; u < NCAND; u++) {
            double vu = sv[u];
            rank += (vu > v) || (vu == v && si[u] < mi);
        }
        s_rank[tid] = rank;
        if (rank == TOPK - 1) s_c31 = tid;
        if (rank == TOPK)     s_c32 = tid;
    }
    __syncthreads();

    if (tid == 0) {
        int c31 = s_c31, c32 = s_c32;
        if (fabs(sv[c31] - sv[c32]) <= TIE_EPS && si[c32] < si[c31]) {
            s_rank[c31] = TOPK;
            s_rank[c32] = TOPK - 1;
        }
    }
    __syncthreads();

    if (tid < NCAND) {
        int rank = s_rank[tid];
        if (rank < TOPK) {
            vals[n * TOPK + rank] = fmaxf((float)sv[tid], 0.f);
            idxs[n * TOPK + rank] = si[tid];
        }
    }
}

// ---------------- fused output: zero+scatter sparse, decode ----------------
__global__ __launch_bounds__(256) void output_kernel(
    const float* __restrict__ vals, const int* __restrict__ idxs,
    const float* __restrict__ WdecT, const float* __restrict__ b_dec,
    float* __restrict__ xhat, float* __restrict__ sparse)
{
    const int n   = blockIdx.x;
    const int tid = threadIdx.x;
    __shared__ float sv[TOPK];
    __shared__ int   si[TOPK];
    if (tid < TOPK) { sv[tid] = vals[n * TOPK + tid]; si[tid] = idxs[n * TOPK + tid]; }
    __syncthreads();

    float4* row4 = reinterpret_cast<float4*>(sparse + (size_t)n * DDICT);
    const float4 z4 = make_float4(0.f, 0.f, 0.f, 0.f);
    for (int i = tid; i < DDICT / 4; i += 256) row4[i] = z4;

    float a0 = b_dec[tid], a1 = b_dec[tid + 256], a2 = b_dec[tid + 512];
#pragma unroll
    for (int k = 0; k < TOPK; k++) {
        const float* w = WdecT + (size_t)si[k] * DMODEL;
        const float v = sv[k];
        a0 = fmaf(v, w[tid],       a0);
        a1 = fmaf(v, w[tid + 256], a1);
        a2 = fmaf(v, w[tid + 512], a2);
    }
    float* o = xhat + (size_t)n * DMODEL;
    o[tid] = a0; o[tid + 256] = a1; o[tid + 512] = a2;

    __syncthreads();
    if (tid < TOPK)
        sparse[(size_t)n * DDICT + si[tid]] = sv[tid];
}

// ---------------- launch ----------------
extern "C" void kernel_launch(void* const* d_in, const int* in_sizes, int n_in,
                              void* d_out, int out_size)
{
    const float* x     = (const float*)d_in[0];
    const float* W_enc = (const float*)d_in[1];
    const float* b_enc = (const float*)d_in[2];
    const float* W_dec = (const float*)d_in[3];
    const float* b_dec = (const float*)d_in[4];

    float* xhat   = (float*)d_out;
    float* sparse = (float*)d_out + (size_t)NROWS * DMODEL;

    __nv_bfloat16* xb; cudaGetSymbolAddress((void**)&xb, g_xb);
    __nv_bfloat16* wb; cudaGetSymbolAddress((void**)&wb, g_wb);
    float*    WdecT; cudaGetSymbolAddress((void**)&WdecT, g_WdecT);
    float*    vals;  cudaGetSymbolAddress((void**)&vals,  g_vals);
    int*      idx;   cudaGetSymbolAddress((void**)&idx,   g_idx);
    int*      cand;  cudaGetSymbolAddress((void**)&cand,  g_cand);
    uint32_t* cbuf;  cudaGetSymbolAddress((void**)&cbuf,  g_cbuf);
    int*      ccnt;  cudaGetSymbolAddress((void**)&ccnt,  g_ccnt);
    uint16_t* tkey;  cudaGetSymbolAddress((void**)&tkey,  g_tkey);

    row_thresh_kernel<<<NROWS / 8, 256>>>(x, tkey, ccnt);

    {
        int n4 = NROWS * DMODEL / 4;
        convert_bf16_kernel<<<(n4 + 255) / 256, 256>>>(x, xb, n4);
        n4 = DDICT * DMODEL / 4;
        convert_bf16_kernel<<<(n4 + 255) / 256, 256>>>(W_enc, wb, n4);
    }

    transpose_wdec_kernel<<<dim3(DDICT / 32, DMODEL / 32), dim3(32, 8)>>>(W_dec, WdecT);

    // bf16 tensor-core candidate GEMM (128x128 tile, 3-stage, 2 CTA/SM)
    cudaFuncSetAttribute(gemm_bf16_kernel, cudaFuncAttributeMaxDynamicSharedMemorySize,
                         SMEM_TOTAL_G);
    gemm_bf16_kernel<<<dim3(DDICT / 128, NROWS / 128), 256, SMEM_TOTAL_G>>>(
        xb, wb, b_enc, tkey, ccnt, cbuf);

    top48_kernel<<<NROWS, 256>>>(ccnt, cbuf, cand);

    rescore_kernel<<<NROWS, 256>>>(x, W_enc, b_enc, cand, vals, idx);

    output_kernel<<<NROWS, 256>>>(vals, idx, WdecT, b_dec, xhat, sparse);
}

// round 13
// speedup vs baseline: 1.1869x; 1.0962x over previous
#include <cuda_runtime.h>
#include <cuda_bf16.h>
#include <cstdint>
#include <cstddef>

#define NROWS   8192
#define DMODEL  768
#define DDICT   24576
#define TOPK    32
#define NCAND   48
#define CAP     1024
#define TIE_EPS 1.0e-6

// ---------------- scratch (static device arrays; no cudaMalloc) ----------------
__device__ __align__(16) __nv_bfloat16  g_xb[(size_t)NROWS * DMODEL];
__device__ __align__(16) __nv_bfloat16  g_wb[(size_t)DDICT * DMODEL];
__device__ float    g_WdecT[(size_t)DDICT * DMODEL];
__device__ float    g_vals[NROWS * TOPK];
__device__ int      g_idx [NROWS * TOPK];
__device__ int      g_cand[NROWS * NCAND];
__device__ uint32_t g_cbuf[(size_t)NROWS * CAP];
__device__ int      g_ccnt[NROWS];
__device__ uint16_t g_tkey[NROWS];

// ---------------- order-preserving bf16 key ----------------
__device__ __forceinline__ uint16_t key1(float v)
{
    uint16_t r = __bfloat16_as_ushort(__float2bfloat16_rn(v));
    uint16_t mask = (r & 0x8000u) ? 0xFFFFu : 0x8000u;
    return (uint16_t)(r ^ mask);
}

// ---------------- per-row threshold + counter reset ----------------
__global__ __launch_bounds__(256) void row_thresh_kernel(
    const float* __restrict__ x, uint16_t* __restrict__ tkey, int* __restrict__ ccnt)
{
    const int row  = blockIdx.x * 8 + (threadIdx.x >> 5);
    const int lane = threadIdx.x & 31;
    const float* xr = x + (size_t)row * DMODEL;
    float s = 0.f;
#pragma unroll
    for (int d = lane; d < DMODEL; d += 32) { float v = xr[d]; s = fmaf(v, v, s); }
#pragma unroll
    for (int off = 16; off > 0; off >>= 1)
        s += __shfl_down_sync(0xFFFFFFFFu, s, off);
    if (lane == 0) {
        float sigma = sqrtf(s * (1.0f / DMODEL));
        float t = 2.55f * sigma - 0.06f;
        tkey[row] = key1(t);
        ccnt[row] = 0;
    }
}

// ---------------- fp32 -> bf16 conversion ----------------
__global__ __launch_bounds__(256) void convert_bf16_kernel(
    const float* __restrict__ src, __nv_bfloat16* __restrict__ dst, int n4)
{
    int i = blockIdx.x * 256 + threadIdx.x;
    if (i < n4) {
        float4 v = reinterpret_cast<const float4*>(src)[i];
        uint32_t p0, p1;
        asm("cvt.rn.bf16x2.f32 %0, %1, %2;" : "=r"(p0) : "f"(v.y), "f"(v.x));
        asm("cvt.rn.bf16x2.f32 %0, %1, %2;" : "=r"(p1) : "f"(v.w), "f"(v.z));
        reinterpret_cast<uint2*>(dst)[i] = make_uint2(p0, p1);
    }
}

// ---------------- W_dec transpose ----------------
__global__ __launch_bounds__(256) void transpose_wdec_kernel(
    const float* __restrict__ Wdec, float* __restrict__ WdecT)
{
    __shared__ float tile[32][33];
    int x = blockIdx.x * 32 + threadIdx.x;
    int y = blockIdx.y * 32 + threadIdx.y;
#pragma unroll
    for (int j = 0; j < 32; j += 8)
        tile[threadIdx.y + j][threadIdx.x] = Wdec[(size_t)(y + j) * DDICT + x];
    __syncthreads();
    int xo = blockIdx.y * 32 + threadIdx.x;
    int yo = blockIdx.x * 32 + threadIdx.y;
#pragma unroll
    for (int j = 0; j < 32; j += 8)
        WdecT[(size_t)(yo + j) * DMODEL + xo] = tile[threadIdx.x][threadIdx.y + j];
}

// ---------------- mma.sync helpers (proven round-5 mapping) ----------------
__device__ __forceinline__ void ldsm_x4(uint32_t& r0, uint32_t& r1, uint32_t& r2,
                                        uint32_t& r3, uint32_t a)
{
    asm volatile("ldmatrix.sync.aligned.m8n8.x4.shared.b16 {%0,%1,%2,%3}, [%4];"
                 : "=r"(r0), "=r"(r1), "=r"(r2), "=r"(r3) : "r"(a));
}

__device__ __forceinline__ void mma_16816(float* c, uint32_t a0, uint32_t a1,
                                          uint32_t a2, uint32_t a3,
                                          uint32_t b0, uint32_t b1)
{
    asm volatile("mma.sync.aligned.m16n8k16.row.col.f32.bf16.bf16.f32 "
                 "{%0,%1,%2,%3}, {%4,%5,%6,%7}, {%8,%9}, {%0,%1,%2,%3};"
                 : "+f"(c[0]), "+f"(c[1]), "+f"(c[2]), "+f"(c[3])
                 : "r"(a0), "r"(a1), "r"(a2), "r"(a3), "r"(b0), "r"(b1));
}

__device__ __forceinline__ void push_cand(int row, int col, float v, uint16_t tk,
                                          int* ccnt, uint32_t* cbuf)
{
    uint16_t k = key1(v);
    if (k > tk) {
        int pos = atomicAdd(&ccnt[row], 1);
        if (pos < CAP)
            cbuf[(size_t)row * CAP + pos] = ((uint32_t)k << 15) | (uint32_t)col;
    }
}

#define CPA16(dst, src) asm volatile( \
    "cp.async.cg.shared.global [%0], [%1], 16;" :: "r"(dst), "l"(src))

// ---------------- bf16 candidate GEMM: 128x128, 256 thr, 2-stage, 1 sync/iter --
__global__ __launch_bounds__(256) void gemm_bf16_kernel(
    const __nv_bfloat16* __restrict__ A,   // xb  [NROWS, DMODEL]
    const __nv_bfloat16* __restrict__ B,   // wb  [DDICT, DMODEL]
    const float* __restrict__ bias,
    const uint16_t* __restrict__ tkey,
    int* __restrict__ ccnt,
    uint32_t* __restrict__ cbuf)
{
    constexpr int LDS = 80;                 // smem row pitch (32 bf16 + 16B pad)
    __shared__ __align__(16) unsigned char As[2][128 * LDS];
    __shared__ __align__(16) unsigned char Bs[2][128 * LDS];

    const int tid  = threadIdx.x;
    const int lane = tid & 31;
    const int wid  = tid >> 5;
    const int bm   = blockIdx.y * 128;
    const int bn   = blockIdx.x * 128;
    const int wm   = (wid & 1) * 64;        // 2 warps in M
    const int wn   = (wid >> 1) * 32;       // 4 warps in N

    const int r0 = tid >> 2, c8 = (tid & 3) * 8;
    const __nv_bfloat16* gA0 = A + (size_t)(bm + r0)      * DMODEL + c8;
    const __nv_bfloat16* gA1 = A + (size_t)(bm + r0 + 64) * DMODEL + c8;
    const __nv_bfloat16* gB0 = B + (size_t)(bn + r0)      * DMODEL + c8;
    const __nv_bfloat16* gB1 = B + (size_t)(bn + r0 + 64) * DMODEL + c8;
    const uint32_t aBase = (uint32_t)__cvta_generic_to_shared(As);
    const uint32_t bBase = (uint32_t)__cvta_generic_to_shared(Bs);
    const uint32_t dA0 = r0 * LDS + c8 * 2;
    const uint32_t dA1 = (r0 + 64) * LDS + c8 * 2;

    const int rowin = (lane & 7) + ((lane >> 3) & 1) * 8;
    const int kxa   = (lane >> 4) * 16;
    const int rowb  = wn + (lane >> 4) * 8 + (lane & 7);
    const int kxb   = ((lane >> 3) & 1) * 16;

    float acc[4][4][4];
#pragma unroll
    for (int i = 0; i < 4; i++)
#pragma unroll
        for (int j = 0; j < 4; j++)
#pragma unroll
            for (int q = 0; q < 4; q++) acc[i][j][q] = 0.f;

    // prologue: chunk 0 -> stage 0
    {
        const uint32_t ab = aBase, bb = bBase;
        CPA16(ab + dA0, gA0); CPA16(ab + dA1, gA1);
        CPA16(bb + dA0, gB0); CPA16(bb + dA1, gB1);
        asm volatile("cp.async.commit_group;");
    }

    for (int it = 0; it < DMODEL / 32; it++) {
        // group `it` resident (committed last iteration / prologue)
        asm volatile("cp.async.wait_group 0;");
        __syncthreads();   // all warps done computing stage it&1^1 from iter it-1

        // issue next chunk into the stage last read at iter it-1 (now free)
        if (it + 1 < DMODEL / 32) {
            const uint32_t off = ((it + 1) & 1) * (128 * LDS);
            const int ke = (it + 1) * 32;
            CPA16(aBase + off + dA0, gA0 + ke); CPA16(aBase + off + dA1, gA1 + ke);
            CPA16(bBase + off + dA0, gB0 + ke); CPA16(bBase + off + dA1, gB1 + ke);
            asm volatile("cp.async.commit_group;");
        }

        const uint32_t aB = aBase + (it & 1) * (128 * LDS);
        const uint32_t bB = bBase + (it & 1) * (128 * LDS);
#pragma unroll
        for (int ks = 0; ks < 2; ks++) {
            uint32_t af[4][4];
#pragma unroll
            for (int mt = 0; mt < 4; mt++)
                ldsm_x4(af[mt][0], af[mt][1], af[mt][2], af[mt][3],
                        aB + (uint32_t)((wm + mt * 16 + rowin) * LDS + ks * 32 + kxa));
            uint32_t bf[4][2];
#pragma unroll
            for (int p = 0; p < 2; p++) {
                uint32_t t0, t1, t2, t3;
                ldsm_x4(t0, t1, t2, t3,
                        bB + (uint32_t)((rowb + p * 16) * LDS + ks * 32 + kxb));
                bf[2 * p][0] = t0; bf[2 * p][1] = t1;
                bf[2 * p + 1][0] = t2; bf[2 * p + 1][1] = t3;
            }
#pragma unroll
            for (int mt = 0; mt < 4; mt++)
#pragma unroll
                for (int nt = 0; nt < 4; nt++)
                    mma_16816(acc[mt][nt], af[mt][0], af[mt][1], af[mt][2],
                              af[mt][3], bf[nt][0], bf[nt][1]);
        }
        // no trailing sync: next iteration's sync (after wait) provides the
        // ordering before any warp overwrites the stage read here.
    }

    // epilogue: +bias, threshold-compare, push candidates (round-7 proven)
    float bb0[4], bb1[4];
    int   ncol[4];
#pragma unroll
    for (int nt = 0; nt < 4; nt++) {
        ncol[nt] = bn + wn + nt * 8 + (lane & 3) * 2;
        bb0[nt] = bias[ncol[nt]];
        bb1[nt] = bias[ncol[nt] + 1];
    }
#pragma unroll
    for (int mt = 0; mt < 4; mt++) {
        const int mlo = bm + wm + mt * 16 + (lane >> 2);
        const int mhi = mlo + 8;
        const uint16_t tlo = tkey[mlo];
        const uint16_t thi = tkey[mhi];
#pragma unroll
        for (int nt = 0; nt < 4; nt++) {
            push_cand(mlo, ncol[nt],     acc[mt][nt][0] + bb0[nt], tlo, ccnt, cbuf);
            push_cand(mlo, ncol[nt] + 1, acc[mt][nt][1] + bb1[nt], tlo, ccnt, cbuf);
            push_cand(mhi, ncol[nt],     acc[mt][nt][2] + bb0[nt], thi, ccnt, cbuf);
            push_cand(mhi, ncol[nt] + 1, acc[mt][nt][3] + bb1[nt], thi, ccnt, cbuf);
        }
    }
}

// ---------------- top-48 of candidate pool ----------------
__global__ __launch_bounds__(256) void top48_kernel(
    const int* __restrict__ ccnt, const uint32_t* __restrict__ cbuf,
    int* __restrict__ cand)
{
    __shared__ uint32_t sp[CAP];
    const int n = blockIdx.x, tid = threadIdx.x;
    const int cnt = min(ccnt[n], CAP);
    for (int i = tid; i < cnt; i += 256) sp[i] = cbuf[(size_t)n * CAP + i];
    __syncthreads();
    for (int t = tid; t < cnt; t += 256) {
        const uint32_t p = sp[t];
        int rank = 0;
        for (int u = 0; u < cnt; u++) rank += (sp[u] > p);
        if (rank < NCAND) cand[n * NCAND + rank] = (int)(p & 0x7FFFu);
    }
    for (int t = tid; t < NCAND; t += 256)
        if (t >= cnt) cand[n * NCAND + t] = t;
}

// ---------------- exact rescore (fp64) + top-32 w/ boundary rule ----------------
__global__ __launch_bounds__(256) void rescore_kernel(
    const float* __restrict__ X, const float* __restrict__ W,
    const float* __restrict__ bias, const int* __restrict__ cand,
    float* __restrict__ vals, int* __restrict__ idxs)
{
    __shared__ float  sx[DMODEL];
    __shared__ double sv[NCAND];
    __shared__ int    si[NCAND];
    __shared__ int    s_rank[NCAND];
    __shared__ int    s_c31, s_c32;

    const int n    = blockIdx.x;
    const int tid  = threadIdx.x;
    const int wid  = tid >> 5;
    const int lane = tid & 31;

    for (int i = tid; i < DMODEL; i += 256) sx[i] = X[(size_t)n * DMODEL + i];
    if (tid < NCAND) si[tid] = cand[n * NCAND + tid];
    __syncthreads();

    for (int c = wid * 6; c < wid * 6 + 6; c++) {
        const int f = si[c];
        const float* w = W + (size_t)f * DMODEL;
        double acc = 0.0;
#pragma unroll
        for (int d = lane; d < DMODEL; d += 32)
            acc += (double)sx[d] * (double)__ldg(&w[d]);
#pragma unroll
        for (int off = 16; off > 0; off >>= 1)
            acc += __shfl_down_sync(0xFFFFFFFFu, acc, off);
        if (lane == 0) sv[c] = acc + (double)bias[f];
    }
    __syncthreads();

    if (tid < NCAND) {
        const double v  = sv[tid];
        const int    mi = si[tid];
        int rank = 0;
#pragma unroll
        for (int u = 0; u < NCAND; u++) {
            double vu = sv[u];
            rank += (vu > v) || (vu == v && si[u] < mi);
        }
        s_rank[tid] = rank;
        if (rank == TOPK - 1) s_c31 = tid;
        if (rank == TOPK)     s_c32 = tid;
    }
    __syncthreads();

    if (tid == 0) {
        int c31 = s_c31, c32 = s_c32;
        if (fabs(sv[c31] - sv[c32]) <= TIE_EPS && si[c32] < si[c31]) {
            s_rank[c31] = TOPK;
            s_rank[c32] = TOPK - 1;
        }
    }
    __syncthreads();

    if (tid < NCAND) {
        int rank = s_rank[tid];
        if (rank < TOPK) {
            vals[n * TOPK + rank] = fmaxf((float)sv[tid], 0.f);
            idxs[n * TOPK + rank] = si[tid];
        }
    }
}

// ---------------- fused output: zero+scatter sparse, decode ----------------
__global__ __launch_bounds__(256) void output_kernel(
    const float* __restrict__ vals, const int* __restrict__ idxs,
    const float* __restrict__ WdecT, const float* __restrict__ b_dec,
    float* __restrict__ xhat, float* __restrict__ sparse)
{
    const int n   = blockIdx.x;
    const int tid = threadIdx.x;
    __shared__ float sv[TOPK];
    __shared__ int   si[TOPK];
    if (tid < TOPK) { sv[tid] = vals[n * TOPK + tid]; si[tid] = idxs[n * TOPK + tid]; }
    __syncthreads();

    float4* row4 = reinterpret_cast<float4*>(sparse + (size_t)n * DDICT);
    const float4 z4 = make_float4(0.f, 0.f, 0.f, 0.f);
    for (int i = tid; i < DDICT / 4; i += 256) row4[i] = z4;

    float a0 = b_dec[tid], a1 = b_dec[tid + 256], a2 = b_dec[tid + 512];
#pragma unroll
    for (int k = 0; k < TOPK; k++) {
        const float* w = WdecT + (size_t)si[k] * DMODEL;
        const float v = sv[k];
        a0 = fmaf(v, w[tid],       a0);
        a1 = fmaf(v, w[tid + 256], a1);
        a2 = fmaf(v, w[tid + 512], a2);
    }
    float* o = xhat + (size_t)n * DMODEL;
    o[tid] = a0; o[tid + 256] = a1; o[tid + 512] = a2;

    __syncthreads();
    if (tid < TOPK)
        sparse[(size_t)n * DDICT + si[tid]] = sv[tid];
}

// ---------------- launch ----------------
extern "C" void kernel_launch(void* const* d_in, const int* in_sizes, int n_in,
                              void* d_out, int out_size)
{
    const float* x     = (const float*)d_in[0];
    const float* W_enc = (const float*)d_in[1];
    const float* b_enc = (const float*)d_in[2];
    const float* W_dec = (const float*)d_in[3];
    const float* b_dec = (const float*)d_in[4];

    float* xhat   = (float*)d_out;
    float* sparse = (float*)d_out + (size_t)NROWS * DMODEL;

    __nv_bfloat16* xb; cudaGetSymbolAddress((void**)&xb, g_xb);
    __nv_bfloat16* wb; cudaGetSymbolAddress((void**)&wb, g_wb);
    float*    WdecT; cudaGetSymbolAddress((void**)&WdecT, g_WdecT);
    float*    vals;  cudaGetSymbolAddress((void**)&vals,  g_vals);
    int*      idx;   cudaGetSymbolAddress((void**)&idx,   g_idx);
    int*      cand;  cudaGetSymbolAddress((void**)&cand,  g_cand);
    uint32_t* cbuf;  cudaGetSymbolAddress((void**)&cbuf,  g_cbuf);
    int*      ccnt;  cudaGetSymbolAddress((void**)&ccnt,  g_ccnt);
    uint16_t* tkey;  cudaGetSymbolAddress((void**)&tkey,  g_tkey);

    row_thresh_kernel<<<NROWS / 8, 256>>>(x, tkey, ccnt);

    {
        int n4 = NROWS * DMODEL / 4;
        convert_bf16_kernel<<<(n4 + 255) / 256, 256>>>(x, xb, n4);
        n4 = DDICT * DMODEL / 4;
        convert_bf16_kernel<<<(n4 + 255) / 256, 256>>>(W_enc, wb, n4);
    }

    transpose_wdec_kernel<<<dim3(DDICT / 32, DMODEL / 32), dim3(32, 8)>>>(W_dec, WdecT);

    // bf16 tensor-core candidate GEMM (128x128 tile, 2-stage, 1 sync/iter)
    gemm_bf16_kernel<<<dim3(DDICT / 128, NROWS / 128), 256>>>(
        xb, wb, b_enc, tkey, ccnt, cbuf);

    top48_kernel<<<NROWS, 256>>>(ccnt, cbuf, cand);

    rescore_kernel<<<NROWS, 256>>>(x, W_enc, b_enc, cand, vals, idx);

    output_kernel<<<NROWS, 256>>>(vals, idx, WdecT, b_dec, xhat, sparse);
}